// round 15
// baseline (speedup 1.0000x reference)
#include <cuda_runtime.h>
#include <cuda_bf16.h>
#include <cstdint>

#define VOCAB   50000
#define NQUADS  4096                 // cell-quads: 4 cells, 32 int4 tokens
#define TABLE_BYTES (VOCAB * 4)      // 200000 B (multiple of 16)

__device__ float g_proj[VOCAB];

// 32-byte L2-evict_last load (legal form on sm_103: ld...v4.b64)
struct f8 { float4 a, b; };
__device__ __forceinline__ f8 ldg_el8(const void* p) {
    unsigned long long x0, x1, x2, x3;
    asm volatile("ld.global.nc.L2::evict_last.v4.b64 {%0,%1,%2,%3}, [%4];"
                 : "=l"(x0), "=l"(x1), "=l"(x2), "=l"(x3) : "l"(p));
    f8 r;
    r.a.x = __uint_as_float((unsigned)(x0));
    r.a.y = __uint_as_float((unsigned)(x0 >> 32));
    r.a.z = __uint_as_float((unsigned)(x1));
    r.a.w = __uint_as_float((unsigned)(x1 >> 32));
    r.b.x = __uint_as_float((unsigned)(x2));
    r.b.y = __uint_as_float((unsigned)(x2 >> 32));
    r.b.z = __uint_as_float((unsigned)(x3));
    r.b.w = __uint_as_float((unsigned)(x3 >> 32));
    return r;
}
__device__ __forceinline__ float dot8(const f8& v, const float4& w0, const float4& w1) {
    float s = 0.f;
    s = fmaf(v.a.x, w0.x, s); s = fmaf(v.a.y, w0.y, s);
    s = fmaf(v.a.z, w0.z, s); s = fmaf(v.a.w, w0.w, s);
    s = fmaf(v.b.x, w1.x, s); s = fmaf(v.b.y, w1.y, s);
    s = fmaf(v.b.z, w1.z, s); s = fmaf(v.b.w, w1.w, s);
    return s;
}

// ---------------------------------------------------------------------------
// Kernel 1 (unchanged R14 champion): p[v] = dot(E[v,:], W).
// ---------------------------------------------------------------------------
__global__ void __launch_bounds__(256) proj_kernel(
    const float* __restrict__ E,
    const float* __restrict__ W)
{
    int gwarp = (blockIdx.x * blockDim.x + threadIdx.x) >> 5;
    int lane  = threadIdx.x & 31;
    int row0  = gwarp * 4;
    if (row0 >= VOCAB) return;

    const char* __restrict__ Eb = reinterpret_cast<const char*>(E);
    const float4* __restrict__ w4 = reinterpret_cast<const float4*>(W);

    float4 w0 = w4[lane * 2];
    float4 w1 = w4[lane * 2 + 1];

    size_t off = (size_t)row0 * 1024 + lane * 32;
    f8 r0 = ldg_el8(Eb + off);
    f8 r1 = ldg_el8(Eb + off + 1024);
    f8 r2 = ldg_el8(Eb + off + 2048);
    f8 r3 = ldg_el8(Eb + off + 3072);

    float s0 = dot8(r0, w0, w1);
    float s1 = dot8(r1, w0, w1);
    float s2 = dot8(r2, w0, w1);
    float s3 = dot8(r3, w0, w1);

    #pragma unroll
    for (int o = 16; o > 0; o >>= 1) {
        s0 += __shfl_xor_sync(0xFFFFFFFFu, s0, o);
        s1 += __shfl_xor_sync(0xFFFFFFFFu, s1, o);
        s2 += __shfl_xor_sync(0xFFFFFFFFu, s2, o);
        s3 += __shfl_xor_sync(0xFFFFFFFFu, s3, o);
    }
    if (lane == 0) {
        g_proj[row0 + 0] = s0;
        g_proj[row0 + 1] = s1;
        g_proj[row0 + 2] = s2;
        g_proj[row0 + 3] = s3;
    }
}

// ---------------------------------------------------------------------------
// Kernel 2: R14 skeleton, but the fill is 4 x 50 KB TMA bulk copies
// (cp.async.bulk) into one mbarrier — zero per-thread L1tex requests.
// Stream-ordered launch (no PDL). x prefetched under the fill.
// ---------------------------------------------------------------------------
__global__ void __launch_bounds__(1024) gather_kernel(
    const int*   __restrict__ x,
    const float* __restrict__ bias,
    float*       __restrict__ out)
{
    extern __shared__ float s_proj[];          // 200000 B
    __shared__ __align__(8) uint64_t mbar;

    int tid  = threadIdx.x;
    int lane = tid & 31;
    int wid  = tid >> 5;
    int gw   = blockIdx.x * 32 + wid;          // 0..4095

    uint32_t mbar_addr = (uint32_t)__cvta_generic_to_shared(&mbar);
    if (tid == 0) {
        asm volatile("mbarrier.init.shared.b64 [%0], 1;" :: "r"(mbar_addr) : "memory");
        asm volatile("fence.proxy.async.shared::cta;" ::: "memory");
    }
    __syncthreads();

    // ---- TMA bulk fill: 4 ops, one engine stream, no thread-request cost ----
    if (tid == 0) {
        asm volatile("mbarrier.arrive.expect_tx.shared.b64 _, [%0], %1;"
                     :: "r"(mbar_addr), "r"((uint32_t)TABLE_BYTES) : "memory");
        uint32_t sdst = (uint32_t)__cvta_generic_to_shared(s_proj);
        const char* src = reinterpret_cast<const char*>(g_proj);
        #pragma unroll
        for (int c = 0; c < 4; ++c) {
            asm volatile(
                "cp.async.bulk.shared::cta.global.mbarrier::complete_tx::bytes "
                "[%0], [%1], %2, [%3];"
                :: "r"(sdst + c * (TABLE_BYTES / 4)),
                   "l"(src + c * (TABLE_BYTES / 4)),
                   "r"((uint32_t)(TABLE_BYTES / 4)),
                   "r"(mbar_addr)
                : "memory");
        }
    }

    // ---- prefetch tokens + bias while the TMA fill streams ----
    int4 t   = reinterpret_cast<const int4*>(x)[gw * 32 + lane];
    float bv = bias[0];

    // ---- wait for fill completion (phase 0 each launch) ----
    {
        uint32_t done;
        asm volatile(
            "{\n\t"
            ".reg .pred p;\n\t"
            "mbarrier.try_wait.parity.acquire.cta.shared::cta.b64 p, [%1], 0;\n\t"
            "selp.b32 %0, 1, 0, p;\n\t"
            "}"
            : "=r"(done) : "r"(mbar_addr) : "memory");
        if (!done) {
            asm volatile(
                "{\n\t"
                ".reg .pred P1;\n\t"
                "WAIT_LOOP_%=:\n\t"
                "mbarrier.try_wait.parity.acquire.cta.shared::cta.b64 P1, [%0], 0, 0x989680;\n\t"
                "@P1 bra.uni WAIT_DONE_%=;\n\t"
                "bra.uni WAIT_LOOP_%=;\n\t"
                "WAIT_DONE_%=:\n\t"
                "}"
                :: "r"(mbar_addr) : "memory");
        }
    }

    // ---- gather + 8-lane reduce + store ----
    float s = s_proj[t.x] + s_proj[t.y] + s_proj[t.z] + s_proj[t.w];

    s += __shfl_xor_sync(0xFFFFFFFFu, s, 4);
    s += __shfl_xor_sync(0xFFFFFFFFu, s, 2);
    s += __shfl_xor_sync(0xFFFFFFFFu, s, 1);

    if ((lane & 7) == 0) out[gw * 4 + (lane >> 3)] = s + bv;
}

extern "C" void kernel_launch(void* const* d_in, const int* in_sizes, int n_in,
                              void* d_out, int out_size)
{
    const int*   x = (const int*)  d_in[0];
    const float* E = (const float*)d_in[1];
    const float* W = (const float*)d_in[2];
    const float* b = (const float*)d_in[3];
    float* out = (float*)d_out;

    static bool attr_done = false;
    if (!attr_done) {
        cudaFuncSetAttribute(gather_kernel,
                             cudaFuncAttributeMaxDynamicSharedMemorySize,
                             TABLE_BYTES);
        attr_done = true;
    }

    // proj: 12500 row-quads, 8 warps/block -> 1563 blocks
    proj_kernel<<<(VOCAB / 4 + 7) / 8, 256>>>(E, W);
    // gather: 128 blocks x 1024 threads, TMA-filled 200 KB table
    gather_kernel<<<128, 1024, TABLE_BYTES>>>(x, b, out);
}

// round 16
// speedup vs baseline: 1.0175x; 1.0175x over previous
#include <cuda_runtime.h>
#include <cuda_bf16.h>
#include <cstdint>

#define VOCAB   50000
#define NQUADS  4096                 // cell-quads: 4 cells, 32 int4 tokens
#define TABLE_BYTES (VOCAB * 4)      // 200000 B

__device__ float g_proj[VOCAB];

// 32-byte L2-evict_last load (legal form on sm_103: ld...v4.b64)
struct f8 { float4 a, b; };
__device__ __forceinline__ f8 ldg_el8(const void* p) {
    unsigned long long x0, x1, x2, x3;
    asm volatile("ld.global.nc.L2::evict_last.v4.b64 {%0,%1,%2,%3}, [%4];"
                 : "=l"(x0), "=l"(x1), "=l"(x2), "=l"(x3) : "l"(p));
    f8 r;
    r.a.x = __uint_as_float((unsigned)(x0));
    r.a.y = __uint_as_float((unsigned)(x0 >> 32));
    r.a.z = __uint_as_float((unsigned)(x1));
    r.a.w = __uint_as_float((unsigned)(x1 >> 32));
    r.b.x = __uint_as_float((unsigned)(x2));
    r.b.y = __uint_as_float((unsigned)(x2 >> 32));
    r.b.z = __uint_as_float((unsigned)(x3));
    r.b.w = __uint_as_float((unsigned)(x3 >> 32));
    return r;
}
__device__ __forceinline__ float dot8(const f8& v, const float4& w0, const float4& w1) {
    float s = 0.f;
    s = fmaf(v.a.x, w0.x, s); s = fmaf(v.a.y, w0.y, s);
    s = fmaf(v.a.z, w0.z, s); s = fmaf(v.a.w, w0.w, s);
    s = fmaf(v.b.x, w1.x, s); s = fmaf(v.b.y, w1.y, s);
    s = fmaf(v.b.z, w1.z, s); s = fmaf(v.b.w, w1.w, s);
    return s;
}

// ---------------------------------------------------------------------------
// Kernel 1 (R14 champion, unchanged): p[v] = dot(E[v,:], W).
// 4 rows/warp, 4 front-batched 32B evict_last loads per thread.
// ---------------------------------------------------------------------------
__global__ void __launch_bounds__(256) proj_kernel(
    const float* __restrict__ E,
    const float* __restrict__ W)
{
    int gwarp = (blockIdx.x * blockDim.x + threadIdx.x) >> 5;
    int lane  = threadIdx.x & 31;
    int row0  = gwarp * 4;
    if (row0 >= VOCAB) return;

    const char* __restrict__ Eb = reinterpret_cast<const char*>(E);
    const float4* __restrict__ w4 = reinterpret_cast<const float4*>(W);

    float4 w0 = w4[lane * 2];
    float4 w1 = w4[lane * 2 + 1];

    size_t off = (size_t)row0 * 1024 + lane * 32;
    f8 r0 = ldg_el8(Eb + off);
    f8 r1 = ldg_el8(Eb + off + 1024);
    f8 r2 = ldg_el8(Eb + off + 2048);
    f8 r3 = ldg_el8(Eb + off + 3072);

    float s0 = dot8(r0, w0, w1);
    float s1 = dot8(r1, w0, w1);
    float s2 = dot8(r2, w0, w1);
    float s3 = dot8(r3, w0, w1);

    #pragma unroll
    for (int o = 16; o > 0; o >>= 1) {
        s0 += __shfl_xor_sync(0xFFFFFFFFu, s0, o);
        s1 += __shfl_xor_sync(0xFFFFFFFFu, s1, o);
        s2 += __shfl_xor_sync(0xFFFFFFFFu, s2, o);
        s3 += __shfl_xor_sync(0xFFFFFFFFu, s3, o);
    }
    if (lane == 0) {
        g_proj[row0 + 0] = s0;
        g_proj[row0 + 1] = s1;
        g_proj[row0 + 2] = s2;
        g_proj[row0 + 3] = s3;
    }
}

// ---------------------------------------------------------------------------
// Kernel 2 (R14 champion, unchanged): 128 blocks x 1024 threads, 200 KB smem
// table via cp.async fill, x prefetched under the fill, LDS gathers,
// 8-lane reduce, direct store.
// ---------------------------------------------------------------------------
__global__ void __launch_bounds__(1024) gather_kernel(
    const int*   __restrict__ x,
    const float* __restrict__ bias,
    float*       __restrict__ out)
{
    extern __shared__ float s_proj[];   // 200000 B

    uint32_t sbase = (uint32_t)__cvta_generic_to_shared(s_proj);
    const float4* __restrict__ g4 = reinterpret_cast<const float4*>(g_proj);
    for (int i = threadIdx.x; i < VOCAB / 4; i += 1024) {
        asm volatile("cp.async.cg.shared.global [%0], [%1], 16;"
                     :: "r"(sbase + i * 16), "l"(g4 + i));
    }
    asm volatile("cp.async.commit_group;");

    int wid  = threadIdx.x >> 5;
    int lane = threadIdx.x & 31;
    int gw   = blockIdx.x * 32 + wid;          // 0..4095 == NQUADS-1
    int4 t   = reinterpret_cast<const int4*>(x)[gw * 32 + lane];
    float bv = bias[0];

    asm volatile("cp.async.wait_group 0;" ::: "memory");
    __syncthreads();

    float s = s_proj[t.x] + s_proj[t.y] + s_proj[t.z] + s_proj[t.w];

    s += __shfl_xor_sync(0xFFFFFFFFu, s, 4);
    s += __shfl_xor_sync(0xFFFFFFFFu, s, 2);
    s += __shfl_xor_sync(0xFFFFFFFFu, s, 1);

    if ((lane & 7) == 0) out[gw * 4 + (lane >> 3)] = s + bv;
}

extern "C" void kernel_launch(void* const* d_in, const int* in_sizes, int n_in,
                              void* d_out, int out_size)
{
    const int*   x = (const int*)  d_in[0];
    const float* E = (const float*)d_in[1];
    const float* W = (const float*)d_in[2];
    const float* b = (const float*)d_in[3];
    float* out = (float*)d_out;

    static bool attr_done = false;
    if (!attr_done) {
        cudaFuncSetAttribute(gather_kernel,
                             cudaFuncAttributeMaxDynamicSharedMemorySize,
                             TABLE_BYTES);
        // Pin BOTH kernels to the max-shared carveout so the L1/smem split is
        // never reconfigured between back-to-back launches in the replay loop.
        cudaFuncSetAttribute(gather_kernel,
                             cudaFuncAttributePreferredSharedMemoryCarveout, 100);
        cudaFuncSetAttribute(proj_kernel,
                             cudaFuncAttributePreferredSharedMemoryCarveout, 100);
        attr_done = true;
    }

    // proj: 12500 row-quads, 8 warps/block -> 1563 blocks
    proj_kernel<<<(VOCAB / 4 + 7) / 8, 256>>>(E, W);
    // gather: 128 blocks x 1024 threads, one cell-quad per warp
    gather_kernel<<<128, 1024, TABLE_BYTES>>>(x, b, out);
}